// round 14
// baseline (speedup 1.0000x reference)
#include <cuda_runtime.h>
#include <cuda_bf16.h>
#include <math.h>
#include <stdint.h>

#define MR 8192
#define DIN 4096
#define DOUT 4096
#define RK 64

__device__ float g_P[MR * RK];
__device__ float g_Ppart[4 * MR * RK];
__device__ float g_U[MR * RK];
__device__ float g_Wm[DIN * RK];
__device__ float g_Wpart[8 * DIN * RK];
__device__ float g_Gp[32 * RK * RK];
__device__ float g_G[RK * RK];
__device__ float g_Linv[RK * RK];
__device__ float g_S[RK];
__device__ __nv_bfloat16 g_Rbf[MR * DIN];
__device__ __nv_bfloat16 g_Wbf[DOUT * DIN];
__device__ __nv_bfloat16 g_ULbf[MR * RK];
__device__ __nv_bfloat16 g_Mhi[DOUT * RK];
__device__ __nv_bfloat16 g_Mlo[DOUT * RK];
__device__ int8_t g_Wi8[DOUT * DIN];
__device__ int8_t g_Vt8[RK * DIN];
__device__ float g_M[DOUT * RK];
__device__ unsigned g_amax[4];

__device__ __forceinline__ float qlv(float x, float s) {
    float a = fabsf(x / s);
    float lv = 0.0f;
    lv = (a > 0.25f) ? 0.5f : lv;
    lv = (a > 0.75f) ? 1.0f : lv;
    lv = (a > 1.25f) ? 1.5f : lv;
    lv = (a > 1.75f) ? 2.0f : lv;
    lv = (a > 2.5f)  ? 3.0f : lv;
    lv = (a > 3.5f)  ? 4.0f : lv;
    lv = (a > 5.0f)  ? 6.0f : lv;
    return (x < 0.0f) ? -lv : lv;
}
__device__ __forceinline__ int qi8(float x, float s) {
    float a = fabsf(x / s);
    int lv = 0;
    lv = (a > 0.25f) ? 1  : lv;
    lv = (a > 0.75f) ? 2  : lv;
    lv = (a > 1.25f) ? 3  : lv;
    lv = (a > 1.75f) ? 4  : lv;
    lv = (a > 2.5f)  ? 6  : lv;
    lv = (a > 3.5f)  ? 8  : lv;
    lv = (a > 5.0f)  ? 12 : lv;
    return (x < 0.0f) ? -lv : lv;
}
__device__ __forceinline__ float getscale(int slot) {
    return fmaxf(__uint_as_float(g_amax[slot]) / 6.0f, 1e-8f);
}

__device__ __forceinline__ void mma16816(float* c, const uint32_t* a, const uint32_t* b) {
    asm volatile("mma.sync.aligned.m16n8k16.row.col.f32.bf16.bf16.f32 "
                 "{%0,%1,%2,%3}, {%4,%5,%6,%7}, {%8,%9}, {%0,%1,%2,%3};"
                 : "+f"(c[0]), "+f"(c[1]), "+f"(c[2]), "+f"(c[3])
                 : "r"(a[0]), "r"(a[1]), "r"(a[2]), "r"(a[3]), "r"(b[0]), "r"(b[1]));
}
__device__ __forceinline__ void ldsm4(uint32_t* r, uint32_t addr) {
    asm volatile("ldmatrix.sync.aligned.m8n8.x4.shared.b16 {%0,%1,%2,%3}, [%4];"
                 : "=r"(r[0]), "=r"(r[1]), "=r"(r[2]), "=r"(r[3]) : "r"(addr));
}
__device__ __forceinline__ uint32_t smem_u32(const void* p) {
    uint32_t a;
    asm("{ .reg .u64 t; cvta.to.shared.u64 t, %1; cvt.u32.u64 %0, t; }" : "=r"(a) : "l"(p));
    return a;
}
__device__ __forceinline__ void cpa16(uint32_t s, const void* g) {
    asm volatile("cp.async.cg.shared.global [%0], [%1], 16;" :: "r"(s), "l"(g));
}
#define CPA_COMMIT() asm volatile("cp.async.commit_group;" ::: "memory")
#define CPA_WAIT2()  asm volatile("cp.async.wait_group 2;" ::: "memory")

__global__ void k_init() { if (threadIdx.x < 4) g_amax[threadIdx.x] = 0u; }

// ---------------- SVD pipeline ----------------
__global__ __launch_bounds__(256) void k_xb(const float* __restrict__ X,
                                            const float* __restrict__ B,
                                            float* __restrict__ Cp) {
    __shared__ __align__(16) float As[32][68];
    __shared__ __align__(16) float Bs[32][68];
    int m0 = blockIdx.x * 64, k0 = blockIdx.y * 1024, tid = threadIdx.x;
    int tm = tid >> 4, tn = tid & 15;
    int ar = tid >> 3, ac = (tid & 7) * 4;
    int br = tid >> 4, bc = (tid & 15) * 4;
    float acc[4][4] = {};
    for (int kt = 0; kt < 1024; kt += 32) {
#pragma unroll
        for (int p = 0; p < 2; p++) {
            float4 v = *(const float4*)&X[(size_t)(m0 + ar + p * 32) * DIN + k0 + kt + ac];
            int mm = ar + p * 32;
            As[ac + 0][mm] = v.x; As[ac + 1][mm] = v.y;
            As[ac + 2][mm] = v.z; As[ac + 3][mm] = v.w;
            *(float4*)&Bs[br + p * 16][bc] =
                *(const float4*)&B[(size_t)(k0 + kt + br + p * 16) * RK + bc];
        }
        __syncthreads();
#pragma unroll
        for (int k = 0; k < 32; k++) {
            float4 a = *(const float4*)&As[k][tm * 4];
            float4 b = *(const float4*)&Bs[k][tn * 4];
            float av[4] = {a.x, a.y, a.z, a.w}, bv[4] = {b.x, b.y, b.z, b.w};
#pragma unroll
            for (int i = 0; i < 4; i++)
#pragma unroll
                for (int j = 0; j < 4; j++) acc[i][j] += av[i] * bv[j];
        }
        __syncthreads();
    }
    float* C = Cp + (size_t)blockIdx.y * MR * RK;
#pragma unroll
    for (int i = 0; i < 4; i++)
#pragma unroll
        for (int j = 0; j < 4; j++)
            C[(size_t)(m0 + tm * 4 + i) * RK + tn * 4 + j] = acc[i][j];
}

__global__ void k_reduce(const float* __restrict__ parts, float* __restrict__ dst,
                         int n, int nparts) {
    for (int i = blockIdx.x * blockDim.x + threadIdx.x; i < n; i += gridDim.x * blockDim.x) {
        float s = 0.f;
        for (int t = 0; t < nparts; t++) s += parts[(size_t)t * n + i];
        dst[i] = s;
    }
}

__global__ __launch_bounds__(256) void k_gram(const float* __restrict__ P,
                                              float* __restrict__ Gp) {
    __shared__ __align__(16) float Ps[64][68];
    int c = blockIdx.x, tid = threadIdx.x;
    int ti = tid >> 4, tj = tid & 15;
    int row = tid >> 4, c4 = (tid & 15) * 4;
    float acc[4][4] = {};
    for (int t = 0; t < 4; t++) {
        int base = c * 256 + t * 64;
#pragma unroll
        for (int p = 0; p < 4; p++)
            *(float4*)&Ps[row + p * 16][c4] =
                *(const float4*)&P[(size_t)(base + row + p * 16) * RK + c4];
        __syncthreads();
#pragma unroll 8
        for (int mm = 0; mm < 64; mm++) {
            float4 a = *(const float4*)&Ps[mm][ti * 4];
            float4 b = *(const float4*)&Ps[mm][tj * 4];
            float av[4] = {a.x, a.y, a.z, a.w}, bv[4] = {b.x, b.y, b.z, b.w};
#pragma unroll
            for (int i = 0; i < 4; i++)
#pragma unroll
                for (int j = 0; j < 4; j++) acc[i][j] += av[i] * bv[j];
        }
        __syncthreads();
    }
#pragma unroll
    for (int i = 0; i < 4; i++)
#pragma unroll
        for (int j = 0; j < 4; j++)
            Gp[(size_t)c * RK * RK + (ti * 4 + i) * RK + tj * 4 + j] = acc[i][j];
}

__global__ void k_chol(const float* __restrict__ G, float* __restrict__ Linv) {
    __shared__ float A[64][65];
    __shared__ float Li[64][65];
    int tid = threadIdx.x;
    for (int i = tid; i < 4096; i += 64) A[i >> 6][i & 63] = G[i];
    __syncthreads();
    for (int j = 0; j < 64; j++) {
        if (tid == 0) A[j][j] = sqrtf(fmaxf(A[j][j], 1e-30f));
        __syncthreads();
        for (int i = j + 1 + tid; i < 64; i += 64) A[i][j] /= A[j][j];
        __syncthreads();
        for (int i = j + 1 + tid; i < 64; i += 64) {
            float lij = A[i][j];
            for (int k = j + 1; k <= i; k++) A[i][k] -= lij * A[k][j];
        }
        __syncthreads();
    }
    {
        int c = tid;
        Li[c][c] = 1.0f / A[c][c];
        for (int i = c + 1; i < 64; i++) {
            float s = 0.f;
            for (int k = c; k < i; k++) s += A[i][k] * Li[k][c];
            Li[i][c] = -s / A[i][i];
        }
    }
    __syncthreads();
    for (int i = tid; i < 4096; i += 64) {
        int r = i >> 6, k = i & 63;
        Linv[i] = (k <= r) ? Li[r][k] : 0.0f;
    }
}

__global__ __launch_bounds__(256) void k_applyr(const float* __restrict__ P,
                                                const float* __restrict__ Linv,
                                                float* __restrict__ U, int doAmax) {
    __shared__ __align__(16) float Ps[64][68];
    __shared__ float Li[64][65];
    int m0 = blockIdx.x * 64, tid = threadIdx.x;
    int row = tid >> 4, c4 = (tid & 15) * 4;
#pragma unroll
    for (int p = 0; p < 4; p++)
        *(float4*)&Ps[row + p * 16][c4] =
            *(const float4*)&P[(size_t)(m0 + row + p * 16) * RK + c4];
    for (int i = tid; i < 4096; i += 256) Li[i >> 6][i & 63] = Linv[i];
    __syncthreads();
    int ta = tid >> 4, tr = tid & 15;
    float acc[4][4] = {};
#pragma unroll 4
    for (int k = 0; k < 64; k++) {
        float av[4], bv[4];
#pragma unroll
        for (int i = 0; i < 4; i++) av[i] = Ps[ta * 4 + i][k];
#pragma unroll
        for (int j = 0; j < 4; j++) bv[j] = Li[tr * 4 + j][k];
#pragma unroll
        for (int i = 0; i < 4; i++)
#pragma unroll
            for (int j = 0; j < 4; j++) acc[i][j] += av[i] * bv[j];
    }
    float lmax = 0.f;
#pragma unroll
    for (int i = 0; i < 4; i++)
#pragma unroll
        for (int j = 0; j < 4; j++) {
            U[(size_t)(m0 + ta * 4 + i) * RK + tr * 4 + j] = acc[i][j];
            lmax = fmaxf(lmax, fabsf(acc[i][j]));
        }
    if (doAmax) {
        __shared__ float red[256];
        red[tid] = lmax;
        __syncthreads();
        for (int s = 128; s > 0; s >>= 1) {
            if (tid < s) red[tid] = fmaxf(red[tid], red[tid + s]);
            __syncthreads();
        }
        if (tid == 0) atomicMax(&g_amax[1], __float_as_uint(red[0]));
    }
}

__global__ __launch_bounds__(256) void k_xtu(const float* __restrict__ X,
                                             const float* __restrict__ U,
                                             float* __restrict__ Wp) {
    __shared__ __align__(16) float Xs[32][68];
    __shared__ __align__(16) float Us[32][68];
    int n0 = blockIdx.x * 64, m0 = blockIdx.y * 1024, tid = threadIdx.x;
    int ta = tid & 15, tr = tid >> 4;
    int row = tid >> 4, c4 = (tid & 15) * 4;
    float acc[4][4] = {};
    for (int mt = 0; mt < 1024; mt += 32) {
#pragma unroll
        for (int p = 0; p < 2; p++) {
            *(float4*)&Xs[row + p * 16][c4] =
                *(const float4*)&X[(size_t)(m0 + mt + row + p * 16) * DIN + n0 + c4];
            *(float4*)&Us[row + p * 16][c4] =
                *(const float4*)&U[(size_t)(m0 + mt + row + p * 16) * RK + c4];
        }
        __syncthreads();
#pragma unroll
        for (int mm = 0; mm < 32; mm++) {
            float4 a = *(const float4*)&Xs[mm][ta * 4];
            float4 b = *(const float4*)&Us[mm][tr * 4];
            float av[4] = {a.x, a.y, a.z, a.w}, bv[4] = {b.x, b.y, b.z, b.w};
#pragma unroll
            for (int i = 0; i < 4; i++)
#pragma unroll
                for (int j = 0; j < 4; j++) acc[i][j] += av[i] * bv[j];
        }
        __syncthreads();
    }
    float* W = Wp + (size_t)blockIdx.y * DIN * RK;
#pragma unroll
    for (int i = 0; i < 4; i++)
#pragma unroll
        for (int j = 0; j < 4; j++)
            W[(size_t)(n0 + ta * 4 + i) * RK + tr * 4 + j] = acc[i][j];
}

__global__ void k_colnorm(float* __restrict__ W, float* __restrict__ S,
                          int storeS, int nrows) {
    int r = blockIdx.x, tid = threadIdx.x;
    float s = 0.f;
    for (int n = tid; n < nrows; n += 256) {
        float v = W[(size_t)n * RK + r];
        s += v * v;
    }
    __shared__ float red[256];
    red[tid] = s;
    __syncthreads();
    for (int st = 128; st > 0; st >>= 1) {
        if (tid < st) red[tid] += red[tid + st];
        __syncthreads();
    }
    __shared__ float invs;
    if (tid == 0) {
        float nm = sqrtf(red[0]);
        if (storeS) S[r] = nm;
        invs = 1.0f / (nm + 1e-8f);
    }
    __syncthreads();
    float iv = invs;
    float lmax = 0.f;
    for (int n = tid; n < nrows; n += 256) {
        float v = W[(size_t)n * RK + r] * iv;
        W[(size_t)n * RK + r] = v;
        lmax = fmaxf(lmax, fabsf(v));
    }
    if (storeS) {
        __syncthreads();
        red[tid] = lmax;
        __syncthreads();
        for (int st = 128; st > 0; st >>= 1) {
            if (tid < st) red[tid] = fmaxf(red[tid], red[tid + st]);
            __syncthreads();
        }
        if (tid == 0) atomicMax(&g_amax[2], __float_as_uint(red[0]));
    }
}

__global__ void k_amax(const float* __restrict__ p, int n, int slot) {
    float m = 0.f;
    for (int i = blockIdx.x * blockDim.x + threadIdx.x; i < n; i += gridDim.x * blockDim.x)
        m = fmaxf(m, fabsf(p[i]));
    __shared__ float red[256];
    red[threadIdx.x] = m;
    __syncthreads();
    for (int s = 128; s > 0; s >>= 1) {
        if (threadIdx.x < s) red[threadIdx.x] = fmaxf(red[threadIdx.x], red[threadIdx.x + s]);
        __syncthreads();
    }
    if (threadIdx.x == 0) atomicMax(&g_amax[slot], __float_as_uint(red[0]));
}

// residual two-pass: mode 0 = amax only; mode 1 = quantize -> Rbf
__global__ __launch_bounds__(256) void k_resid(const float* __restrict__ X,
                                               const float* __restrict__ U,
                                               const float* __restrict__ S,
                                               const float* __restrict__ V,
                                               __nv_bfloat16* __restrict__ Rbf, int mode) {
    __shared__ __align__(16) float Ut[64][68];
    __shared__ __align__(16) float Vt[64][68];
    __shared__ float Ss[64];
    int m0 = blockIdx.x * 64, n0 = blockIdx.y * 64, tid = threadIdx.x;
    if (tid < 64) Ss[tid] = S[tid];
    __syncthreads();
    float sR = getscale(0);
    int row = tid >> 4, c4 = (tid & 15) * 4;
#pragma unroll
    for (int p = 0; p < 4; p++) {
        int rr = row + p * 16;
        float4 v = *(const float4*)&U[(size_t)(m0 + rr) * RK + c4];
        Ut[c4 + 0][rr] = v.x * Ss[c4 + 0];
        Ut[c4 + 1][rr] = v.y * Ss[c4 + 1];
        Ut[c4 + 2][rr] = v.z * Ss[c4 + 2];
        Ut[c4 + 3][rr] = v.w * Ss[c4 + 3];
        float4 w = *(const float4*)&V[(size_t)(n0 + rr) * RK + c4];
        Vt[c4 + 0][rr] = w.x; Vt[c4 + 1][rr] = w.y;
        Vt[c4 + 2][rr] = w.z; Vt[c4 + 3][rr] = w.w;
    }
    __syncthreads();
    int tm = tid >> 4, tn = tid & 15;
    float acc[4][4] = {};
#pragma unroll 8
    for (int k = 0; k < 64; k++) {
        float4 a = *(const float4*)&Ut[k][tm * 4];
        float4 b = *(const float4*)&Vt[k][tn * 4];
        float av[4] = {a.x, a.y, a.z, a.w}, bv[4] = {b.x, b.y, b.z, b.w};
#pragma unroll
        for (int i = 0; i < 4; i++)
#pragma unroll
            for (int j = 0; j < 4; j++) acc[i][j] += av[i] * bv[j];
    }
    float lmax = 0.f;
#pragma unroll
    for (int i = 0; i < 4; i++) {
        size_t off = (size_t)(m0 + tm * 4 + i) * DIN + n0 + tn * 4;
        float4 xv = *(const float4*)&X[off];
        float rx = xv.x - acc[i][0], ry = xv.y - acc[i][1];
        float rz = xv.z - acc[i][2], rw = xv.w - acc[i][3];
        if (mode == 0) {
            lmax = fmaxf(lmax, fmaxf(fmaxf(fabsf(rx), fabsf(ry)),
                                     fmaxf(fabsf(rz), fabsf(rw))));
        } else {
            __nv_bfloat162* d2 = (__nv_bfloat162*)(Rbf + off);
            d2[0] = __floats2bfloat162_rn(qlv(rx, sR), qlv(ry, sR));
            d2[1] = __floats2bfloat162_rn(qlv(rz, sR), qlv(rw, sR));
        }
    }
    if (mode == 0) {
        __shared__ float red[256];
        red[tid] = lmax;
        __syncthreads();
        for (int s = 128; s > 0; s >>= 1) {
            if (tid < s) red[tid] = fmaxf(red[tid], red[tid + s]);
            __syncthreads();
        }
        if (tid == 0) atomicMax(&g_amax[0], __float_as_uint(red[0]));
    }
}

// ---------------- quantizers ----------------
__global__ void k_qbf(const float* __restrict__ src, __nv_bfloat16* __restrict__ dst,
                      int n4, int slot) {
    float s = getscale(slot);
    for (int i = blockIdx.x * blockDim.x + threadIdx.x; i < n4; i += gridDim.x * blockDim.x) {
        float4 v = ((const float4*)src)[i];
        __nv_bfloat162* d2 = (__nv_bfloat162*)dst;
        d2[i * 2 + 0] = __floats2bfloat162_rn(qlv(v.x, s), qlv(v.y, s));
        d2[i * 2 + 1] = __floats2bfloat162_rn(qlv(v.z, s), qlv(v.w, s));
    }
}
__global__ void k_qw(const float* __restrict__ src, char4* __restrict__ d8,
                     __nv_bfloat16* __restrict__ dbf, int n4) {
    float s = getscale(3);
    for (int i = blockIdx.x * blockDim.x + threadIdx.x; i < n4; i += gridDim.x * blockDim.x) {
        float4 v = ((const float4*)src)[i];
        int ix = qi8(v.x, s), iy = qi8(v.y, s), iz = qi8(v.z, s), iw = qi8(v.w, s);
        char4 c; c.x = (char)ix; c.y = (char)iy; c.z = (char)iz; c.w = (char)iw;
        d8[i] = c;
        __nv_bfloat162* d2 = (__nv_bfloat162*)dbf;
        d2[i * 2 + 0] = __floats2bfloat162_rn(0.5f * ix, 0.5f * iy);
        d2[i * 2 + 1] = __floats2bfloat162_rn(0.5f * iz, 0.5f * iw);
    }
}
__global__ void k_vq8(const float* __restrict__ V, int8_t* __restrict__ Vt8) {
    float s = getscale(2);
    for (int i = blockIdx.x * blockDim.x + threadIdx.x; i < DIN * RK; i += gridDim.x * blockDim.x) {
        int n = i >> 6, r = i & 63;
        Vt8[(size_t)r * DIN + n] = (int8_t)qi8(V[i], s);
    }
}

__global__ __launch_bounds__(256) void k_M(const int8_t* __restrict__ Wi8,
                                           const int8_t* __restrict__ Vt8,
                                           float* __restrict__ M) {
    __shared__ int Ws[4][1024];
    int j0 = blockIdx.x * 4, tid = threadIdx.x;
    {
        int rr = tid >> 6, t = tid & 63;
        const int4* src = (const int4*)(Wi8 + (size_t)(j0 + rr) * DIN);
#pragma unroll
        for (int q = 0; q < 4; q++) {
            int4 v = src[t + q * 64];
            *(int4*)&Ws[rr][(t + q * 64) * 4] = v;
        }
    }
    __syncthreads();
    int jl = tid & 3, r = tid >> 2;
    const int* vr = (const int*)(Vt8 + (size_t)r * DIN);
    int acc = 0;
    for (int k = 0; k < 1024; k++) acc = __dp4a(Ws[jl][k], vr[k], acc);
    float sc = getscale(3) * getscale(2) * 0.25f;
    M[(size_t)(j0 + jl) * RK + r] = (float)acc * sc;
}

__global__ void k_msplit(const float* __restrict__ M, const float* __restrict__ S,
                         __nv_bfloat16* __restrict__ Mhi, __nv_bfloat16* __restrict__ Mlo) {
    float f = getscale(1) / (getscale(0) * getscale(3));
    for (int i = blockIdx.x * blockDim.x + threadIdx.x; i < DOUT * RK;
         i += gridDim.x * blockDim.x) {
        float v = f * S[i & 63] * M[i];
        __nv_bfloat16 h = __float2bfloat16(v);
        Mhi[i] = h;
        Mlo[i] = __float2bfloat16(v - __bfloat162float(h));
    }
}

// out = bias + sc * [ Rbf@Wbf^T + UL@Mhi^T + UL@Mlo^T ]  (132 k-steps)
__global__ __launch_bounds__(256, 2) void k_hmma(const __nv_bfloat16* __restrict__ A,
                                                 const __nv_bfloat16* __restrict__ B,
                                                 const __nv_bfloat16* __restrict__ UL,
                                                 const __nv_bfloat16* __restrict__ Mhi,
                                                 const __nv_bfloat16* __restrict__ Mlo,
                                                 const float* __restrict__ bias,
                                                 float* __restrict__ C) {
    extern __shared__ __align__(16) char dsm[];
    uint32_t base = smem_u32(dsm);
    int tid = threadIdx.x, lane = tid & 31, wid = tid >> 5;
    int m0 = blockIdx.x * 128, j0 = blockIdx.y * 128;
    int wm = (wid & 1) * 64, wn = (wid >> 1) * 32;
    int g = lane >> 2, tg = (lane & 3) * 2;
    float acc[4][4][4] = {};

    int r0 = tid >> 2, r1 = r0 + 64;
    int segB = (tid & 3) * 16;
    const char* Ag = (const char*)A + (size_t)m0 * DIN * 2 + segB;
    const char* Bg = (const char*)B + (size_t)j0 * DIN * 2 + segB;
    const char* Ug = (const char*)UL + (size_t)m0 * 128 + segB;
    const char* Hg = (const char*)Mhi + (size_t)j0 * 128 + segB;
    const char* Lg = (const char*)Mlo + (size_t)j0 * 128 + segB;
    uint32_t sA0 = base + r0 * 80 + segB;
    uint32_t sA1 = base + r1 * 80 + segB;
    uint32_t sB0 = base + 40960 + r0 * 80 + segB;
    uint32_t sB1 = base + 40960 + r1 * 80 + segB;

    int rowA = wm + (lane & 7) + ((lane >> 3) & 1) * 8;
    uint32_t offA = base + rowA * 80 + ((lane >> 4) & 1) * 16;
    int rowB = wn + (lane & 7) + ((lane >> 4) & 1) * 8;
    uint32_t offB = base + 40960 + rowB * 80 + ((lane >> 3) & 1) * 16;

#define ISSUE_LOAD(ks) do {                                              \
    uint32_t _so = ((ks) & 3) * 10240;                                   \
    if ((ks) < 128) {                                                    \
        size_t _go = (size_t)(ks) * 64;                                  \
        cpa16(sA0 + _so, Ag + (size_t)r0 * (DIN * 2) + _go);             \
        cpa16(sA1 + _so, Ag + (size_t)r1 * (DIN * 2) + _go);             \
        cpa16(sB0 + _so, Bg + (size_t)r0 * (DIN * 2) + _go);             \
        cpa16(sB1 + _so, Bg + (size_t)r1 * (DIN * 2) + _go);             \
    } else {                                                             \
        int _t = (ks) - 128;                                             \
        size_t _co = (size_t)(_t & 1) * 64;                              \
        const char* _bm = (_t < 2) ? Hg : Lg;                            \
        cpa16(sA0 + _so, Ug + (size_t)r0 * 128 + _co);                   \
        cpa16(sA1 + _so, Ug + (size_t)r1 * 128 + _co);                   \
        cpa16(sB0 + _so, _bm + (size_t)r0 * 128 + _co);                  \
        cpa16(sB1 + _so, _bm + (size_t)r1 * 128 + _co);                  \
    }                                                                    \
} while (0)

    for (int p = 0; p < 3; p++) {
        ISSUE_LOAD(p);
        CPA_COMMIT();
    }

    for (int kt = 0; kt < 132; kt++) {
        int s = kt & 3;
        CPA_WAIT2();
        __syncthreads();
        // issue next-stage loads FIRST so copies overlap the compute below
        if (kt + 3 < 132) ISSUE_LOAD(kt + 3);
        CPA_COMMIT();
        uint32_t aS = offA + s * 10240;
        uint32_t bS = offB + s * 10240;
#pragma unroll
        for (int h = 0; h < 2; h++) {
            uint32_t af[4][4], bt[2][4];
#pragma unroll
            for (int mt = 0; mt < 4; mt++)
                ldsm4(af[mt], aS + mt * 1280 + h * 32);
            ldsm4(bt[0], bS + h * 32);
            ldsm4(bt[1], bS + 1280 + h * 32);
            uint32_t* bf[4] = {&bt[0][0], &bt[0][2], &bt[1][0], &bt[1][2]};
#pragma unroll
            for (int mt = 0; mt < 4; mt++)
#pragma unroll
                for (int nt = 0; nt < 4; nt++)
                    mma16816(acc[mt][nt], af[mt], bf[nt]);
        }
        __syncthreads();
    }

    float sc = getscale(0) * getscale(3);
#pragma unroll
    for (int mt = 0; mt < 4; mt++) {
        int r = m0 + wm + mt * 16 + g;
#pragma unroll
        for (int nt = 0; nt < 4; nt++) {
            int col = j0 + wn + nt * 8 + tg;
            float2 bv = *(const float2*)&bias[col];
            float2 v0 = make_float2(bv.x + sc * acc[mt][nt][0],
                                    bv.y + sc * acc[mt][nt][1]);
            *(float2*)&C[(size_t)r * DOUT + col] = v0;
            float2 v1 = make_float2(bv.x + sc * acc[mt][nt][2],
                                    bv.y + sc * acc[mt][nt][3]);
            *(float2*)&C[(size_t)(r + 8) * DOUT + col] = v1;
        }
    }
}

extern "C" void kernel_launch(void* const* d_in, const int* in_sizes, int n_in,
                              void* d_out, int out_size) {
    const float* X = (const float*)d_in[0];
    const float* Wt = (const float*)d_in[1];
    const float* bias = (const float*)d_in[2];
    const float* V0 = (const float*)d_in[3];
    float* out = (float*)d_out;

    float *P, *Pp, *U, *Wm, *Wp, *Gp, *G, *Li, *S, *M;
    int8_t *Wi8, *Vt8;
    __nv_bfloat16 *Rbf, *Wbf, *ULbf, *Mhi, *Mlo;
    cudaGetSymbolAddress((void**)&P, g_P);
    cudaGetSymbolAddress((void**)&Pp, g_Ppart);
    cudaGetSymbolAddress((void**)&U, g_U);
    cudaGetSymbolAddress((void**)&Wm, g_Wm);
    cudaGetSymbolAddress((void**)&Wp, g_Wpart);
    cudaGetSymbolAddress((void**)&Gp, g_Gp);
    cudaGetSymbolAddress((void**)&G, g_G);
    cudaGetSymbolAddress((void**)&Li, g_Linv);
    cudaGetSymbolAddress((void**)&S, g_S);
    cudaGetSymbolAddress((void**)&M, g_M);
    cudaGetSymbolAddress((void**)&Wi8, g_Wi8);
    cudaGetSymbolAddress((void**)&Vt8, g_Vt8);
    cudaGetSymbolAddress((void**)&Rbf, g_Rbf);
    cudaGetSymbolAddress((void**)&Wbf, g_Wbf);
    cudaGetSymbolAddress((void**)&ULbf, g_ULbf);
    cudaGetSymbolAddress((void**)&Mhi, g_Mhi);
    cudaGetSymbolAddress((void**)&Mlo, g_Mlo);

    cudaFuncSetAttribute(k_hmma, cudaFuncAttributeMaxDynamicSharedMemorySize, 81920);

    k_init<<<1, 32>>>();
    const float* Bmat = V0;
    for (int it = 0; it < 2; it++) {
        k_xb<<<dim3(128, 4), 256>>>(X, Bmat, Pp);
        k_reduce<<<512, 256>>>(Pp, P, MR * RK, 4);
        k_gram<<<32, 256>>>(P, Gp);
        k_reduce<<<16, 256>>>(Gp, G, RK * RK, 32);
        k_chol<<<1, 64>>>(G, Li);
        k_applyr<<<128, 256>>>(P, Li, U, it);
        k_xtu<<<dim3(64, 8), 256>>>(X, U, Wp);
        k_reduce<<<256, 256>>>(Wp, Wm, DIN * RK, 8);
        k_colnorm<<<64, 256>>>(Wm, S, it, DIN);
        Bmat = Wm;
    }
    k_amax<<<1024, 256>>>(Wt, DOUT * DIN, 3);
    k_qbf<<<512, 256>>>(U, ULbf, MR * RK / 4, 1);
    k_vq8<<<256, 256>>>(Wm, Vt8);
    k_qw<<<1024, 256>>>(Wt, (char4*)Wi8, Wbf, DOUT * DIN / 4);
    k_resid<<<dim3(128, 64), 256>>>(X, U, S, Wm, Rbf, 0);   // amax pass
    k_resid<<<dim3(128, 64), 256>>>(X, U, S, Wm, Rbf, 1);   // quantize pass
    k_M<<<1024, 256>>>(Wi8, Vt8, M);
    k_msplit<<<256, 256>>>(M, S, Mhi, Mlo);
    k_hmma<<<dim3(64, 32), 256, 81920>>>(Rbf, Wbf, ULbf, Mhi, Mlo, bias, out);
}

// round 15
// speedup vs baseline: 1.0541x; 1.0541x over previous
#include <cuda_runtime.h>
#include <cuda_bf16.h>
#include <math.h>
#include <stdint.h>

#define MR 8192
#define DIN 4096
#define DOUT 4096
#define RK 64

__device__ float g_P[MR * RK];
__device__ float g_Ppart[4 * MR * RK];
__device__ float g_U[MR * RK];
__device__ float g_Wm[DIN * RK];
__device__ float g_Wpart[8 * DIN * RK];
__device__ float g_Gp[32 * RK * RK];
__device__ float g_G[RK * RK];
__device__ float g_Linv[RK * RK];
__device__ float g_S[RK];
__device__ float g_R[MR * DIN];
__device__ __nv_bfloat16 g_Rbf[MR * DIN];
__device__ __nv_bfloat16 g_Wbf[DOUT * DIN];
__device__ __nv_bfloat16 g_ULbf[MR * RK];
__device__ __nv_bfloat16 g_Mhi[DOUT * RK];
__device__ __nv_bfloat16 g_Mlo[DOUT * RK];
__device__ int8_t g_Wi8[DOUT * DIN];
__device__ int8_t g_Vt8[RK * DIN];
__device__ float g_M[DOUT * RK];
__device__ unsigned g_amax[4];

__device__ __forceinline__ float qlv(float x, float s) {
    float a = fabsf(x / s);
    float lv = 0.0f;
    lv = (a > 0.25f) ? 0.5f : lv;
    lv = (a > 0.75f) ? 1.0f : lv;
    lv = (a > 1.25f) ? 1.5f : lv;
    lv = (a > 1.75f) ? 2.0f : lv;
    lv = (a > 2.5f)  ? 3.0f : lv;
    lv = (a > 3.5f)  ? 4.0f : lv;
    lv = (a > 5.0f)  ? 6.0f : lv;
    return (x < 0.0f) ? -lv : lv;
}
__device__ __forceinline__ int qi8(float x, float s) {
    float a = fabsf(x / s);
    int lv = 0;
    lv = (a > 0.25f) ? 1  : lv;
    lv = (a > 0.75f) ? 2  : lv;
    lv = (a > 1.25f) ? 3  : lv;
    lv = (a > 1.75f) ? 4  : lv;
    lv = (a > 2.5f)  ? 6  : lv;
    lv = (a > 3.5f)  ? 8  : lv;
    lv = (a > 5.0f)  ? 12 : lv;
    return (x < 0.0f) ? -lv : lv;
}
__device__ __forceinline__ float getscale(int slot) {
    return fmaxf(__uint_as_float(g_amax[slot]) / 6.0f, 1e-8f);
}

__device__ __forceinline__ void mma16816(float* c, const uint32_t* a, const uint32_t* b) {
    asm volatile("mma.sync.aligned.m16n8k16.row.col.f32.bf16.bf16.f32 "
                 "{%0,%1,%2,%3}, {%4,%5,%6,%7}, {%8,%9}, {%0,%1,%2,%3};"
                 : "+f"(c[0]), "+f"(c[1]), "+f"(c[2]), "+f"(c[3])
                 : "r"(a[0]), "r"(a[1]), "r"(a[2]), "r"(a[3]), "r"(b[0]), "r"(b[1]));
}
__device__ __forceinline__ void ldsm4(uint32_t* r, uint32_t addr) {
    asm volatile("ldmatrix.sync.aligned.m8n8.x4.shared.b16 {%0,%1,%2,%3}, [%4];"
                 : "=r"(r[0]), "=r"(r[1]), "=r"(r[2]), "=r"(r[3]) : "r"(addr));
}
__device__ __forceinline__ uint32_t smem_u32(const void* p) {
    uint32_t a;
    asm("{ .reg .u64 t; cvta.to.shared.u64 t, %1; cvt.u32.u64 %0, t; }" : "=r"(a) : "l"(p));
    return a;
}
__device__ __forceinline__ void cpa16(uint32_t s, const void* g) {
    asm volatile("cp.async.cg.shared.global [%0], [%1], 16;" :: "r"(s), "l"(g));
}
#define CPA_COMMIT() asm volatile("cp.async.commit_group;" ::: "memory")
#define CPA_WAIT2()  asm volatile("cp.async.wait_group 2;" ::: "memory")

__global__ void k_init() { if (threadIdx.x < 4) g_amax[threadIdx.x] = 0u; }

// ---------------- SVD pipeline ----------------
__global__ __launch_bounds__(256) void k_xb(const float* __restrict__ X,
                                            const float* __restrict__ B,
                                            float* __restrict__ Cp) {
    __shared__ __align__(16) float As[32][68];
    __shared__ __align__(16) float Bs[32][68];
    int m0 = blockIdx.x * 64, k0 = blockIdx.y * 1024, tid = threadIdx.x;
    int tm = tid >> 4, tn = tid & 15;
    int ar = tid >> 3, ac = (tid & 7) * 4;
    int br = tid >> 4, bc = (tid & 15) * 4;
    float acc[4][4] = {};
    for (int kt = 0; kt < 1024; kt += 32) {
#pragma unroll
        for (int p = 0; p < 2; p++) {
            float4 v = *(const float4*)&X[(size_t)(m0 + ar + p * 32) * DIN + k0 + kt + ac];
            int mm = ar + p * 32;
            As[ac + 0][mm] = v.x; As[ac + 1][mm] = v.y;
            As[ac + 2][mm] = v.z; As[ac + 3][mm] = v.w;
            *(float4*)&Bs[br + p * 16][bc] =
                *(const float4*)&B[(size_t)(k0 + kt + br + p * 16) * RK + bc];
        }
        __syncthreads();
#pragma unroll
        for (int k = 0; k < 32; k++) {
            float4 a = *(const float4*)&As[k][tm * 4];
            float4 b = *(const float4*)&Bs[k][tn * 4];
            float av[4] = {a.x, a.y, a.z, a.w}, bv[4] = {b.x, b.y, b.z, b.w};
#pragma unroll
            for (int i = 0; i < 4; i++)
#pragma unroll
                for (int j = 0; j < 4; j++) acc[i][j] += av[i] * bv[j];
        }
        __syncthreads();
    }
    float* C = Cp + (size_t)blockIdx.y * MR * RK;
#pragma unroll
    for (int i = 0; i < 4; i++)
#pragma unroll
        for (int j = 0; j < 4; j++)
            C[(size_t)(m0 + tm * 4 + i) * RK + tn * 4 + j] = acc[i][j];
}

__global__ void k_reduce(const float* __restrict__ parts, float* __restrict__ dst,
                         int n, int nparts) {
    for (int i = blockIdx.x * blockDim.x + threadIdx.x; i < n; i += gridDim.x * blockDim.x) {
        float s = 0.f;
        for (int t = 0; t < nparts; t++) s += parts[(size_t)t * n + i];
        dst[i] = s;
    }
}

__global__ __launch_bounds__(256) void k_gram(const float* __restrict__ P,
                                              float* __restrict__ Gp) {
    __shared__ __align__(16) float Ps[64][68];
    int c = blockIdx.x, tid = threadIdx.x;
    int ti = tid >> 4, tj = tid & 15;
    int row = tid >> 4, c4 = (tid & 15) * 4;
    float acc[4][4] = {};
    for (int t = 0; t < 4; t++) {
        int base = c * 256 + t * 64;
#pragma unroll
        for (int p = 0; p < 4; p++)
            *(float4*)&Ps[row + p * 16][c4] =
                *(const float4*)&P[(size_t)(base + row + p * 16) * RK + c4];
        __syncthreads();
#pragma unroll 8
        for (int mm = 0; mm < 64; mm++) {
            float4 a = *(const float4*)&Ps[mm][ti * 4];
            float4 b = *(const float4*)&Ps[mm][tj * 4];
            float av[4] = {a.x, a.y, a.z, a.w}, bv[4] = {b.x, b.y, b.z, b.w};
#pragma unroll
            for (int i = 0; i < 4; i++)
#pragma unroll
                for (int j = 0; j < 4; j++) acc[i][j] += av[i] * bv[j];
        }
        __syncthreads();
    }
#pragma unroll
    for (int i = 0; i < 4; i++)
#pragma unroll
        for (int j = 0; j < 4; j++)
            Gp[(size_t)c * RK * RK + (ti * 4 + i) * RK + tj * 4 + j] = acc[i][j];
}

__global__ void k_chol(const float* __restrict__ G, float* __restrict__ Linv) {
    __shared__ float A[64][65];
    __shared__ float Li[64][65];
    int tid = threadIdx.x;
    for (int i = tid; i < 4096; i += 64) A[i >> 6][i & 63] = G[i];
    __syncthreads();
    for (int j = 0; j < 64; j++) {
        if (tid == 0) A[j][j] = sqrtf(fmaxf(A[j][j], 1e-30f));
        __syncthreads();
        for (int i = j + 1 + tid; i < 64; i += 64) A[i][j] /= A[j][j];
        __syncthreads();
        for (int i = j + 1 + tid; i < 64; i += 64) {
            float lij = A[i][j];
            for (int k = j + 1; k <= i; k++) A[i][k] -= lij * A[k][j];
        }
        __syncthreads();
    }
    {
        int c = tid;
        Li[c][c] = 1.0f / A[c][c];
        for (int i = c + 1; i < 64; i++) {
            float s = 0.f;
            for (int k = c; k < i; k++) s += A[i][k] * Li[k][c];
            Li[i][c] = -s / A[i][i];
        }
    }
    __syncthreads();
    for (int i = tid; i < 4096; i += 64) {
        int r = i >> 6, k = i & 63;
        Linv[i] = (k <= r) ? Li[r][k] : 0.0f;
    }
}

__global__ __launch_bounds__(256) void k_applyr(const float* __restrict__ P,
                                                const float* __restrict__ Linv,
                                                float* __restrict__ U, int doAmax) {
    __shared__ __align__(16) float Ps[64][68];
    __shared__ float Li[64][65];
    int m0 = blockIdx.x * 64, tid = threadIdx.x;
    int row = tid >> 4, c4 = (tid & 15) * 4;
#pragma unroll
    for (int p = 0; p < 4; p++)
        *(float4*)&Ps[row + p * 16][c4] =
            *(const float4*)&P[(size_t)(m0 + row + p * 16) * RK + c4];
    for (int i = tid; i < 4096; i += 256) Li[i >> 6][i & 63] = Linv[i];
    __syncthreads();
    int ta = tid >> 4, tr = tid & 15;
    float acc[4][4] = {};
#pragma unroll 4
    for (int k = 0; k < 64; k++) {
        float av[4], bv[4];
#pragma unroll
        for (int i = 0; i < 4; i++) av[i] = Ps[ta * 4 + i][k];
#pragma unroll
        for (int j = 0; j < 4; j++) bv[j] = Li[tr * 4 + j][k];
#pragma unroll
        for (int i = 0; i < 4; i++)
#pragma unroll
            for (int j = 0; j < 4; j++) acc[i][j] += av[i] * bv[j];
    }
    float lmax = 0.f;
#pragma unroll
    for (int i = 0; i < 4; i++)
#pragma unroll
        for (int j = 0; j < 4; j++) {
            U[(size_t)(m0 + ta * 4 + i) * RK + tr * 4 + j] = acc[i][j];
            lmax = fmaxf(lmax, fabsf(acc[i][j]));
        }
    if (doAmax) {
        __shared__ float red[256];
        red[tid] = lmax;
        __syncthreads();
        for (int s = 128; s > 0; s >>= 1) {
            if (tid < s) red[tid] = fmaxf(red[tid], red[tid + s]);
            __syncthreads();
        }
        if (tid == 0) atomicMax(&g_amax[1], __float_as_uint(red[0]));
    }
}

__global__ __launch_bounds__(256) void k_xtu(const float* __restrict__ X,
                                             const float* __restrict__ U,
                                             float* __restrict__ Wp) {
    __shared__ __align__(16) float Xs[32][68];
    __shared__ __align__(16) float Us[32][68];
    int n0 = blockIdx.x * 64, m0 = blockIdx.y * 1024, tid = threadIdx.x;
    int ta = tid & 15, tr = tid >> 4;
    int row = tid >> 4, c4 = (tid & 15) * 4;
    float acc[4][4] = {};
    for (int mt = 0; mt < 1024; mt += 32) {
#pragma unroll
        for (int p = 0; p < 2; p++) {
            *(float4*)&Xs[row + p * 16][c4] =
                *(const float4*)&X[(size_t)(m0 + mt + row + p * 16) * DIN + n0 + c4];
            *(float4*)&Us[row + p * 16][c4] =
                *(const float4*)&U[(size_t)(m0 + mt + row + p * 16) * RK + c4];
        }
        __syncthreads();
#pragma unroll
        for (int mm = 0; mm < 32; mm++) {
            float4 a = *(const float4*)&Xs[mm][ta * 4];
            float4 b = *(const float4*)&Us[mm][tr * 4];
            float av[4] = {a.x, a.y, a.z, a.w}, bv[4] = {b.x, b.y, b.z, b.w};
#pragma unroll
            for (int i = 0; i < 4; i++)
#pragma unroll
                for (int j = 0; j < 4; j++) acc[i][j] += av[i] * bv[j];
        }
        __syncthreads();
    }
    float* W = Wp + (size_t)blockIdx.y * DIN * RK;
#pragma unroll
    for (int i = 0; i < 4; i++)
#pragma unroll
        for (int j = 0; j < 4; j++)
            W[(size_t)(n0 + ta * 4 + i) * RK + tr * 4 + j] = acc[i][j];
}

__global__ void k_colnorm(float* __restrict__ W, float* __restrict__ S,
                          int storeS, int nrows) {
    int r = blockIdx.x, tid = threadIdx.x;
    float s = 0.f;
    for (int n = tid; n < nrows; n += 256) {
        float v = W[(size_t)n * RK + r];
        s += v * v;
    }
    __shared__ float red[256];
    red[tid] = s;
    __syncthreads();
    for (int st = 128; st > 0; st >>= 1) {
        if (tid < st) red[tid] += red[tid + st];
        __syncthreads();
    }
    __shared__ float invs;
    if (tid == 0) {
        float nm = sqrtf(red[0]);
        if (storeS) S[r] = nm;
        invs = 1.0f / (nm + 1e-8f);
    }
    __syncthreads();
    float iv = invs;
    float lmax = 0.f;
    for (int n = tid; n < nrows; n += 256) {
        float v = W[(size_t)n * RK + r] * iv;
        W[(size_t)n * RK + r] = v;
        lmax = fmaxf(lmax, fabsf(v));
    }
    if (storeS) {
        __syncthreads();
        red[tid] = lmax;
        __syncthreads();
        for (int st = 128; st > 0; st >>= 1) {
            if (tid < st) red[tid] = fmaxf(red[tid], red[tid + st]);
            __syncthreads();
        }
        if (tid == 0) atomicMax(&g_amax[2], __float_as_uint(red[0]));
    }
}

__global__ void k_amax(const float* __restrict__ p, int n, int slot) {
    float m = 0.f;
    for (int i = blockIdx.x * blockDim.x + threadIdx.x; i < n; i += gridDim.x * blockDim.x)
        m = fmaxf(m, fabsf(p[i]));
    __shared__ float red[256];
    red[threadIdx.x] = m;
    __syncthreads();
    for (int s = 128; s > 0; s >>= 1) {
        if (threadIdx.x < s) red[threadIdx.x] = fmaxf(red[threadIdx.x], red[threadIdx.x + s]);
        __syncthreads();
    }
    if (threadIdx.x == 0) atomicMax(&g_amax[slot], __float_as_uint(red[0]));
}

__global__ __launch_bounds__(256) void k_resid(const float* __restrict__ X,
                                               const float* __restrict__ U,
                                               const float* __restrict__ S,
                                               const float* __restrict__ V,
                                               float* __restrict__ R) {
    __shared__ __align__(16) float Ut[64][68];
    __shared__ __align__(16) float Vt[64][68];
    __shared__ float Ss[64];
    int m0 = blockIdx.x * 64, n0 = blockIdx.y * 64, tid = threadIdx.x;
    if (tid < 64) Ss[tid] = S[tid];
    __syncthreads();
    int row = tid >> 4, c4 = (tid & 15) * 4;
#pragma unroll
    for (int p = 0; p < 4; p++) {
        int rr = row + p * 16;
        float4 v = *(const float4*)&U[(size_t)(m0 + rr) * RK + c4];
        Ut[c4 + 0][rr] = v.x * Ss[c4 + 0];
        Ut[c4 + 1][rr] = v.y * Ss[c4 + 1];
        Ut[c4 + 2][rr] = v.z * Ss[c4 + 2];
        Ut[c4 + 3][rr] = v.w * Ss[c4 + 3];
        float4 w = *(const float4*)&V[(size_t)(n0 + rr) * RK + c4];
        Vt[c4 + 0][rr] = w.x; Vt[c4 + 1][rr] = w.y;
        Vt[c4 + 2][rr] = w.z; Vt[c4 + 3][rr] = w.w;
    }
    __syncthreads();
    int tm = tid >> 4, tn = tid & 15;
    float acc[4][4] = {};
#pragma unroll 8
    for (int k = 0; k < 64; k++) {
        float4 a = *(const float4*)&Ut[k][tm * 4];
        float4 b = *(const float4*)&Vt[k][tn * 4];
        float av[4] = {a.x, a.y, a.z, a.w}, bv[4] = {b.x, b.y, b.z, b.w};
#pragma unroll
        for (int i = 0; i < 4; i++)
#pragma unroll
            for (int j = 0; j < 4; j++) acc[i][j] += av[i] * bv[j];
    }
    float lmax = 0.f;
#pragma unroll
    for (int i = 0; i < 4; i++) {
        size_t off = (size_t)(m0 + tm * 4 + i) * DIN + n0 + tn * 4;
        float4 xv = *(const float4*)&X[off];
        float4 rv = make_float4(xv.x - acc[i][0], xv.y - acc[i][1],
                                xv.z - acc[i][2], xv.w - acc[i][3]);
        *(float4*)&R[off] = rv;
        lmax = fmaxf(lmax, fmaxf(fmaxf(fabsf(rv.x), fabsf(rv.y)),
                                 fmaxf(fabsf(rv.z), fabsf(rv.w))));
    }
    __shared__ float red[256];
    red[tid] = lmax;
    __syncthreads();
    for (int s = 128; s > 0; s >>= 1) {
        if (tid < s) red[tid] = fmaxf(red[tid], red[tid + s]);
        __syncthreads();
    }
    if (tid == 0) atomicMax(&g_amax[0], __float_as_uint(red[0]));
}

// ---------------- quantizers ----------------
__global__ void k_qbf(const float* __restrict__ src, __nv_bfloat16* __restrict__ dst,
                      int n4, int slot) {
    float s = getscale(slot);
    for (int i = blockIdx.x * blockDim.x + threadIdx.x; i < n4; i += gridDim.x * blockDim.x) {
        float4 v = ((const float4*)src)[i];
        __nv_bfloat162* d2 = (__nv_bfloat162*)dst;
        d2[i * 2 + 0] = __floats2bfloat162_rn(qlv(v.x, s), qlv(v.y, s));
        d2[i * 2 + 1] = __floats2bfloat162_rn(qlv(v.z, s), qlv(v.w, s));
    }
}
__global__ void k_qw(const float* __restrict__ src, char4* __restrict__ d8,
                     __nv_bfloat16* __restrict__ dbf, int n4) {
    float s = getscale(3);
    for (int i = blockIdx.x * blockDim.x + threadIdx.x; i < n4; i += gridDim.x * blockDim.x) {
        float4 v = ((const float4*)src)[i];
        int ix = qi8(v.x, s), iy = qi8(v.y, s), iz = qi8(v.z, s), iw = qi8(v.w, s);
        char4 c; c.x = (char)ix; c.y = (char)iy; c.z = (char)iz; c.w = (char)iw;
        d8[i] = c;
        __nv_bfloat162* d2 = (__nv_bfloat162*)dbf;
        d2[i * 2 + 0] = __floats2bfloat162_rn(0.5f * ix, 0.5f * iy);
        d2[i * 2 + 1] = __floats2bfloat162_rn(0.5f * iz, 0.5f * iw);
    }
}
__global__ void k_vq8(const float* __restrict__ V, int8_t* __restrict__ Vt8) {
    float s = getscale(2);
    for (int i = blockIdx.x * blockDim.x + threadIdx.x; i < DIN * RK; i += gridDim.x * blockDim.x) {
        int n = i >> 6, r = i & 63;
        Vt8[(size_t)r * DIN + n] = (int8_t)qi8(V[i], s);
    }
}

__global__ __launch_bounds__(256) void k_M(const int8_t* __restrict__ Wi8,
                                           const int8_t* __restrict__ Vt8,
                                           float* __restrict__ M) {
    __shared__ int Ws[4][1024];
    int j0 = blockIdx.x * 4, tid = threadIdx.x;
    {
        int rr = tid >> 6, t = tid & 63;
        const int4* src = (const int4*)(Wi8 + (size_t)(j0 + rr) * DIN);
#pragma unroll
        for (int q = 0; q < 4; q++) {
            int4 v = src[t + q * 64];
            *(int4*)&Ws[rr][(t + q * 64) * 4] = v;
        }
    }
    __syncthreads();
    int jl = tid & 3, r = tid >> 2;
    const int* vr = (const int*)(Vt8 + (size_t)r * DIN);
    int acc = 0;
    for (int k = 0; k < 1024; k++) acc = __dp4a(Ws[jl][k], vr[k], acc);
    float sc = getscale(3) * getscale(2) * 0.25f;
    M[(size_t)(j0 + jl) * RK + r] = (float)acc * sc;
}

__global__ void k_msplit(const float* __restrict__ M, const float* __restrict__ S,
                         __nv_bfloat16* __restrict__ Mhi, __nv_bfloat16* __restrict__ Mlo) {
    float f = getscale(1) / (getscale(0) * getscale(3));
    for (int i = blockIdx.x * blockDim.x + threadIdx.x; i < DOUT * RK;
         i += gridDim.x * blockDim.x) {
        float v = f * S[i & 63] * M[i];
        __nv_bfloat16 h = __float2bfloat16(v);
        Mhi[i] = h;
        Mlo[i] = __float2bfloat16(v - __bfloat162float(h));
    }
}

// out = bias + sc * [ Rbf@Wbf^T + UL@Mhi^T + UL@Mlo^T ]  (132 k-steps)
__global__ __launch_bounds__(256, 2) void k_hmma(const __nv_bfloat16* __restrict__ A,
                                                 const __nv_bfloat16* __restrict__ B,
                                                 const __nv_bfloat16* __restrict__ UL,
                                                 const __nv_bfloat16* __restrict__ Mhi,
                                                 const __nv_bfloat16* __restrict__ Mlo,
                                                 const float* __restrict__ bias,
                                                 float* __restrict__ C) {
    extern __shared__ __align__(16) char dsm[];
    uint32_t base = smem_u32(dsm);
    int tid = threadIdx.x, lane = tid & 31, wid = tid >> 5;
    int m0 = blockIdx.x * 128, j0 = blockIdx.y * 128;
    int wm = (wid & 1) * 64, wn = (wid >> 1) * 32;
    int g = lane >> 2, tg = (lane & 3) * 2;
    float acc[4][4][4] = {};

    int r0 = tid >> 2, r1 = r0 + 64;
    int segB = (tid & 3) * 16;
    const char* Ag = (const char*)A + (size_t)m0 * DIN * 2 + segB;
    const char* Bg = (const char*)B + (size_t)j0 * DIN * 2 + segB;
    const char* Ug = (const char*)UL + (size_t)m0 * 128 + segB;
    const char* Hg = (const char*)Mhi + (size_t)j0 * 128 + segB;
    const char* Lg = (const char*)Mlo + (size_t)j0 * 128 + segB;
    uint32_t sA0 = base + r0 * 80 + segB;
    uint32_t sA1 = base + r1 * 80 + segB;
    uint32_t sB0 = base + 40960 + r0 * 80 + segB;
    uint32_t sB1 = base + 40960 + r1 * 80 + segB;

    int rowA = wm + (lane & 7) + ((lane >> 3) & 1) * 8;
    uint32_t offA = base + rowA * 80 + ((lane >> 4) & 1) * 16;
    int rowB = wn + (lane & 7) + ((lane >> 4) & 1) * 8;
    uint32_t offB = base + 40960 + rowB * 80 + ((lane >> 3) & 1) * 16;

#define ISSUE_LOAD(ks) do {                                              \
    uint32_t _so = ((ks) & 3) * 10240;                                   \
    if ((ks) < 128) {                                                    \
        size_t _go = (size_t)(ks) * 64;                                  \
        cpa16(sA0 + _so, Ag + (size_t)r0 * (DIN * 2) + _go);             \
        cpa16(sA1 + _so, Ag + (size_t)r1 * (DIN * 2) + _go);             \
        cpa16(sB0 + _so, Bg + (size_t)r0 * (DIN * 2) + _go);             \
        cpa16(sB1 + _so, Bg + (size_t)r1 * (DIN * 2) + _go);             \
    } else {                                                             \
        int _t = (ks) - 128;                                             \
        size_t _co = (size_t)(_t & 1) * 64;                              \
        const char* _bm = (_t < 2) ? Hg : Lg;                            \
        cpa16(sA0 + _so, Ug + (size_t)r0 * 128 + _co);                   \
        cpa16(sA1 + _so, Ug + (size_t)r1 * 128 + _co);                   \
        cpa16(sB0 + _so, _bm + (size_t)r0 * 128 + _co);                  \
        cpa16(sB1 + _so, _bm + (size_t)r1 * 128 + _co);                  \
    }                                                                    \
} while (0)

    for (int p = 0; p < 3; p++) {
        ISSUE_LOAD(p);
        CPA_COMMIT();
    }

    for (int kt = 0; kt < 132; kt++) {
        int s = kt & 3;
        CPA_WAIT2();
        __syncthreads();
        if (kt + 3 < 132) ISSUE_LOAD(kt + 3);   // overlap copies with compute
        CPA_COMMIT();
        uint32_t aS = offA + s * 10240;
        uint32_t bS = offB + s * 10240;
#pragma unroll
        for (int h = 0; h < 2; h++) {
            uint32_t af[4][4], bt[2][4];
#pragma unroll
            for (int mt = 0; mt < 4; mt++)
                ldsm4(af[mt], aS + mt * 1280 + h * 32);
            ldsm4(bt[0], bS + h * 32);
            ldsm4(bt[1], bS + 1280 + h * 32);
            uint32_t* bf[4] = {&bt[0][0], &bt[0][2], &bt[1][0], &bt[1][2]};
#pragma unroll
            for (int mt = 0; mt < 4; mt++)
#pragma unroll
                for (int nt = 0; nt < 4; nt++)
                    mma16816(acc[mt][nt], af[mt], bf[nt]);
        }
        __syncthreads();
    }

    float sc = getscale(0) * getscale(3);
#pragma unroll
    for (int mt = 0; mt < 4; mt++) {
        int r = m0 + wm + mt * 16 + g;
#pragma unroll
        for (int nt = 0; nt < 4; nt++) {
            int col = j0 + wn + nt * 8 + tg;
            float2 bv = *(const float2*)&bias[col];
            float2 v0 = make_float2(bv.x + sc * acc[mt][nt][0],
                                    bv.y + sc * acc[mt][nt][1]);
            *(float2*)&C[(size_t)r * DOUT + col] = v0;
            float2 v1 = make_float2(bv.x + sc * acc[mt][nt][2],
                                    bv.y + sc * acc[mt][nt][3]);
            *(float2*)&C[(size_t)(r + 8) * DOUT + col] = v1;
        }
    }
}

extern "C" void kernel_launch(void* const* d_in, const int* in_sizes, int n_in,
                              void* d_out, int out_size) {
    const float* X = (const float*)d_in[0];
    const float* Wt = (const float*)d_in[1];
    const float* bias = (const float*)d_in[2];
    const float* V0 = (const float*)d_in[3];
    float* out = (float*)d_out;

    float *P, *Pp, *U, *Wm, *Wp, *Gp, *G, *Li, *S, *R, *M;
    int8_t *Wi8, *Vt8;
    __nv_bfloat16 *Rbf, *Wbf, *ULbf, *Mhi, *Mlo;
    cudaGetSymbolAddress((void**)&P, g_P);
    cudaGetSymbolAddress((void**)&Pp, g_Ppart);
    cudaGetSymbolAddress((void**)&U, g_U);
    cudaGetSymbolAddress((void**)&Wm, g_Wm);
    cudaGetSymbolAddress((void**)&Wp, g_Wpart);
    cudaGetSymbolAddress((void**)&Gp, g_Gp);
    cudaGetSymbolAddress((void**)&G, g_G);
    cudaGetSymbolAddress((void**)&Li, g_Linv);
    cudaGetSymbolAddress((void**)&S, g_S);
    cudaGetSymbolAddress((void**)&R, g_R);
    cudaGetSymbolAddress((void**)&M, g_M);
    cudaGetSymbolAddress((void**)&Wi8, g_Wi8);
    cudaGetSymbolAddress((void**)&Vt8, g_Vt8);
    cudaGetSymbolAddress((void**)&Rbf, g_Rbf);
    cudaGetSymbolAddress((void**)&Wbf, g_Wbf);
    cudaGetSymbolAddress((void**)&ULbf, g_ULbf);
    cudaGetSymbolAddress((void**)&Mhi, g_Mhi);
    cudaGetSymbolAddress((void**)&Mlo, g_Mlo);

    cudaFuncSetAttribute(k_hmma, cudaFuncAttributeMaxDynamicSharedMemorySize, 81920);

    k_init<<<1, 32>>>();
    const float* Bmat = V0;
    for (int it = 0; it < 2; it++) {
        k_xb<<<dim3(128, 4), 256>>>(X, Bmat, Pp);
        k_reduce<<<512, 256>>>(Pp, P, MR * RK, 4);
        k_gram<<<32, 256>>>(P, Gp);
        k_reduce<<<16, 256>>>(Gp, G, RK * RK, 32);
        k_chol<<<1, 64>>>(G, Li);
        k_applyr<<<128, 256>>>(P, Li, U, it);
        k_xtu<<<dim3(64, 8), 256>>>(X, U, Wp);
        k_reduce<<<256, 256>>>(Wp, Wm, DIN * RK, 8);
        k_colnorm<<<64, 256>>>(Wm, S, it, DIN);
        Bmat = Wm;
    }
    k_amax<<<1024, 256>>>(Wt, DOUT * DIN, 3);
    k_qbf<<<512, 256>>>(U, ULbf, MR * RK / 4, 1);
    k_vq8<<<256, 256>>>(Wm, Vt8);
    k_qw<<<1024, 256>>>(Wt, (char4*)Wi8, Wbf, DOUT * DIN / 4);
    k_resid<<<dim3(128, 64), 256>>>(X, U, S, Wm, R);
    k_qbf<<<2048, 256>>>(R, Rbf, MR * DIN / 4, 0);
    k_M<<<1024, 256>>>(Wi8, Vt8, M);
    k_msplit<<<256, 256>>>(M, S, Mhi, Mlo);
    k_hmma<<<dim3(64, 32), 256, 81920>>>(Rbf, Wbf, ULbf, Mhi, Mlo, bias, out);
}

// round 16
// speedup vs baseline: 1.1027x; 1.0461x over previous
#include <cuda_runtime.h>
#include <cuda_bf16.h>
#include <math.h>
#include <stdint.h>

#define MR 8192
#define DIN 4096
#define DOUT 4096
#define RK 64

__device__ float g_P[MR * RK];
__device__ float g_Ppart[4 * MR * RK];
__device__ float g_U[MR * RK];
__device__ float g_Wm[DIN * RK];
__device__ float g_Wpart[8 * DIN * RK];
__device__ float g_Gp[32 * RK * RK];
__device__ float g_G[RK * RK];
__device__ float g_Linv[RK * RK];
__device__ float g_S[RK];
__device__ float g_R[MR * DIN];
__device__ __nv_bfloat16 g_Rbf[MR * DIN];
__device__ __nv_bfloat16 g_Wbf[DOUT * DIN];
__device__ __nv_bfloat16 g_ULbf[MR * RK];
__device__ __nv_bfloat16 g_Mhi[DOUT * RK];
__device__ __nv_bfloat16 g_Mlo[DOUT * RK];
__device__ int8_t g_Wi8[DOUT * DIN];
__device__ int8_t g_Vt8[RK * DIN];
__device__ float g_M[DOUT * RK];
__device__ unsigned g_amax[4];

__device__ __forceinline__ float qlv(float x, float s) {
    float a = fabsf(x / s);
    float lv = 0.0f;
    lv = (a > 0.25f) ? 0.5f : lv;
    lv = (a > 0.75f) ? 1.0f : lv;
    lv = (a > 1.25f) ? 1.5f : lv;
    lv = (a > 1.75f) ? 2.0f : lv;
    lv = (a > 2.5f)  ? 3.0f : lv;
    lv = (a > 3.5f)  ? 4.0f : lv;
    lv = (a > 5.0f)  ? 6.0f : lv;
    return (x < 0.0f) ? -lv : lv;
}
__device__ __forceinline__ int qi8(float x, float s) {
    float a = fabsf(x / s);
    int lv = 0;
    lv = (a > 0.25f) ? 1  : lv;
    lv = (a > 0.75f) ? 2  : lv;
    lv = (a > 1.25f) ? 3  : lv;
    lv = (a > 1.75f) ? 4  : lv;
    lv = (a > 2.5f)  ? 6  : lv;
    lv = (a > 3.5f)  ? 8  : lv;
    lv = (a > 5.0f)  ? 12 : lv;
    return (x < 0.0f) ? -lv : lv;
}
__device__ __forceinline__ float getscale(int slot) {
    return fmaxf(__uint_as_float(g_amax[slot]) / 6.0f, 1e-8f);
}

__device__ __forceinline__ void mma16816(float* c, const uint32_t* a, const uint32_t* b) {
    asm volatile("mma.sync.aligned.m16n8k16.row.col.f32.bf16.bf16.f32 "
                 "{%0,%1,%2,%3}, {%4,%5,%6,%7}, {%8,%9}, {%0,%1,%2,%3};"
                 : "+f"(c[0]), "+f"(c[1]), "+f"(c[2]), "+f"(c[3])
                 : "r"(a[0]), "r"(a[1]), "r"(a[2]), "r"(a[3]), "r"(b[0]), "r"(b[1]));
}
__device__ __forceinline__ void ldsm4(uint32_t* r, uint32_t addr) {
    asm volatile("ldmatrix.sync.aligned.m8n8.x4.shared.b16 {%0,%1,%2,%3}, [%4];"
                 : "=r"(r[0]), "=r"(r[1]), "=r"(r[2]), "=r"(r[3]) : "r"(addr));
}
__device__ __forceinline__ uint32_t smem_u32(const void* p) {
    uint32_t a;
    asm("{ .reg .u64 t; cvta.to.shared.u64 t, %1; cvt.u32.u64 %0, t; }" : "=r"(a) : "l"(p));
    return a;
}
__device__ __forceinline__ void cpa16(uint32_t s, const void* g) {
    asm volatile("cp.async.cg.shared.global [%0], [%1], 16;" :: "r"(s), "l"(g));
}
#define CPA_COMMIT() asm volatile("cp.async.commit_group;" ::: "memory")
#define CPA_WAIT2()  asm volatile("cp.async.wait_group 2;" ::: "memory")

__global__ void k_init() { if (threadIdx.x < 4) g_amax[threadIdx.x] = 0u; }

// ---------------- SVD pipeline ----------------
__global__ __launch_bounds__(256) void k_xb(const float* __restrict__ X,
                                            const float* __restrict__ B,
                                            float* __restrict__ Cp) {
    __shared__ __align__(16) float As[32][68];
    __shared__ __align__(16) float Bs[32][68];
    int m0 = blockIdx.x * 64, k0 = blockIdx.y * 1024, tid = threadIdx.x;
    int tm = tid >> 4, tn = tid & 15;
    int ar = tid >> 3, ac = (tid & 7) * 4;
    int br = tid >> 4, bc = (tid & 15) * 4;
    float acc[4][4] = {};
    for (int kt = 0; kt < 1024; kt += 32) {
#pragma unroll
        for (int p = 0; p < 2; p++) {
            float4 v = *(const float4*)&X[(size_t)(m0 + ar + p * 32) * DIN + k0 + kt + ac];
            int mm = ar + p * 32;
            As[ac + 0][mm] = v.x; As[ac + 1][mm] = v.y;
            As[ac + 2][mm] = v.z; As[ac + 3][mm] = v.w;
            *(float4*)&Bs[br + p * 16][bc] =
                *(const float4*)&B[(size_t)(k0 + kt + br + p * 16) * RK + bc];
        }
        __syncthreads();
#pragma unroll
        for (int k = 0; k < 32; k++) {
            float4 a = *(const float4*)&As[k][tm * 4];
            float4 b = *(const float4*)&Bs[k][tn * 4];
            float av[4] = {a.x, a.y, a.z, a.w}, bv[4] = {b.x, b.y, b.z, b.w};
#pragma unroll
            for (int i = 0; i < 4; i++)
#pragma unroll
                for (int j = 0; j < 4; j++) acc[i][j] += av[i] * bv[j];
        }
        __syncthreads();
    }
    float* C = Cp + (size_t)blockIdx.y * MR * RK;
#pragma unroll
    for (int i = 0; i < 4; i++)
#pragma unroll
        for (int j = 0; j < 4; j++)
            C[(size_t)(m0 + tm * 4 + i) * RK + tn * 4 + j] = acc[i][j];
}

__global__ void k_reduce(const float* __restrict__ parts, float* __restrict__ dst,
                         int n, int nparts) {
    for (int i = blockIdx.x * blockDim.x + threadIdx.x; i < n; i += gridDim.x * blockDim.x) {
        float s = 0.f;
        for (int t = 0; t < nparts; t++) s += parts[(size_t)t * n + i];
        dst[i] = s;
    }
}

__global__ __launch_bounds__(256) void k_gram(const float* __restrict__ P,
                                              float* __restrict__ Gp) {
    __shared__ __align__(16) float Ps[64][68];
    int c = blockIdx.x, tid = threadIdx.x;
    int ti = tid >> 4, tj = tid & 15;
    int row = tid >> 4, c4 = (tid & 15) * 4;
    float acc[4][4] = {};
    for (int t = 0; t < 4; t++) {
        int base = c * 256 + t * 64;
#pragma unroll
        for (int p = 0; p < 4; p++)
            *(float4*)&Ps[row + p * 16][c4] =
                *(const float4*)&P[(size_t)(base + row + p * 16) * RK + c4];
        __syncthreads();
#pragma unroll 8
        for (int mm = 0; mm < 64; mm++) {
            float4 a = *(const float4*)&Ps[mm][ti * 4];
            float4 b = *(const float4*)&Ps[mm][tj * 4];
            float av[4] = {a.x, a.y, a.z, a.w}, bv[4] = {b.x, b.y, b.z, b.w};
#pragma unroll
            for (int i = 0; i < 4; i++)
#pragma unroll
                for (int j = 0; j < 4; j++) acc[i][j] += av[i] * bv[j];
        }
        __syncthreads();
    }
#pragma unroll
    for (int i = 0; i < 4; i++)
#pragma unroll
        for (int j = 0; j < 4; j++)
            Gp[(size_t)c * RK * RK + (ti * 4 + i) * RK + tj * 4 + j] = acc[i][j];
}

__global__ void k_chol(const float* __restrict__ G, float* __restrict__ Linv) {
    __shared__ float A[64][65];
    __shared__ float Li[64][65];
    int tid = threadIdx.x;
    for (int i = tid; i < 4096; i += 64) A[i >> 6][i & 63] = G[i];
    __syncthreads();
    for (int j = 0; j < 64; j++) {
        if (tid == 0) A[j][j] = sqrtf(fmaxf(A[j][j], 1e-30f));
        __syncthreads();
        for (int i = j + 1 + tid; i < 64; i += 64) A[i][j] /= A[j][j];
        __syncthreads();
        for (int i = j + 1 + tid; i < 64; i += 64) {
            float lij = A[i][j];
            for (int k = j + 1; k <= i; k++) A[i][k] -= lij * A[k][j];
        }
        __syncthreads();
    }
    {
        int c = tid;
        Li[c][c] = 1.0f / A[c][c];
        for (int i = c + 1; i < 64; i++) {
            float s = 0.f;
            for (int k = c; k < i; k++) s += A[i][k] * Li[k][c];
            Li[i][c] = -s / A[i][i];
        }
    }
    __syncthreads();
    for (int i = tid; i < 4096; i += 64) {
        int r = i >> 6, k = i & 63;
        Linv[i] = (k <= r) ? Li[r][k] : 0.0f;
    }
}

__global__ __launch_bounds__(256) void k_applyr(const float* __restrict__ P,
                                                const float* __restrict__ Linv,
                                                float* __restrict__ U, int doAmax) {
    __shared__ __align__(16) float Ps[64][68];
    __shared__ float Li[64][65];
    int m0 = blockIdx.x * 64, tid = threadIdx.x;
    int row = tid >> 4, c4 = (tid & 15) * 4;
#pragma unroll
    for (int p = 0; p < 4; p++)
        *(float4*)&Ps[row + p * 16][c4] =
            *(const float4*)&P[(size_t)(m0 + row + p * 16) * RK + c4];
    for (int i = tid; i < 4096; i += 256) Li[i >> 6][i & 63] = Linv[i];
    __syncthreads();
    int ta = tid >> 4, tr = tid & 15;
    float acc[4][4] = {};
#pragma unroll 4
    for (int k = 0; k < 64; k++) {
        float av[4], bv[4];
#pragma unroll
        for (int i = 0; i < 4; i++) av[i] = Ps[ta * 4 + i][k];
#pragma unroll
        for (int j = 0; j < 4; j++) bv[j] = Li[tr * 4 + j][k];
#pragma unroll
        for (int i = 0; i < 4; i++)
#pragma unroll
            for (int j = 0; j < 4; j++) acc[i][j] += av[i] * bv[j];
    }
    float lmax = 0.f;
#pragma unroll
    for (int i = 0; i < 4; i++)
#pragma unroll
        for (int j = 0; j < 4; j++) {
            U[(size_t)(m0 + ta * 4 + i) * RK + tr * 4 + j] = acc[i][j];
            lmax = fmaxf(lmax, fabsf(acc[i][j]));
        }
    if (doAmax) {
        __shared__ float red[256];
        red[tid] = lmax;
        __syncthreads();
        for (int s = 128; s > 0; s >>= 1) {
            if (tid < s) red[tid] = fmaxf(red[tid], red[tid + s]);
            __syncthreads();
        }
        if (tid == 0) atomicMax(&g_amax[1], __float_as_uint(red[0]));
    }
}

__global__ __launch_bounds__(256) void k_xtu(const float* __restrict__ X,
                                             const float* __restrict__ U,
                                             float* __restrict__ Wp) {
    __shared__ __align__(16) float Xs[32][68];
    __shared__ __align__(16) float Us[32][68];
    int n0 = blockIdx.x * 64, m0 = blockIdx.y * 1024, tid = threadIdx.x;
    int ta = tid & 15, tr = tid >> 4;
    int row = tid >> 4, c4 = (tid & 15) * 4;
    float acc[4][4] = {};
    for (int mt = 0; mt < 1024; mt += 32) {
#pragma unroll
        for (int p = 0; p < 2; p++) {
            *(float4*)&Xs[row + p * 16][c4] =
                *(const float4*)&X[(size_t)(m0 + mt + row + p * 16) * DIN + n0 + c4];
            *(float4*)&Us[row + p * 16][c4] =
                *(const float4*)&U[(size_t)(m0 + mt + row + p * 16) * RK + c4];
        }
        __syncthreads();
#pragma unroll
        for (int mm = 0; mm < 32; mm++) {
            float4 a = *(const float4*)&Xs[mm][ta * 4];
            float4 b = *(const float4*)&Us[mm][tr * 4];
            float av[4] = {a.x, a.y, a.z, a.w}, bv[4] = {b.x, b.y, b.z, b.w};
#pragma unroll
            for (int i = 0; i < 4; i++)
#pragma unroll
                for (int j = 0; j < 4; j++) acc[i][j] += av[i] * bv[j];
        }
        __syncthreads();
    }
    float* W = Wp + (size_t)blockIdx.y * DIN * RK;
#pragma unroll
    for (int i = 0; i < 4; i++)
#pragma unroll
        for (int j = 0; j < 4; j++)
            W[(size_t)(n0 + ta * 4 + i) * RK + tr * 4 + j] = acc[i][j];
}

__global__ void k_colnorm(float* __restrict__ W, float* __restrict__ S,
                          int storeS, int nrows) {
    int r = blockIdx.x, tid = threadIdx.x;
    float s = 0.f;
    for (int n = tid; n < nrows; n += 256) {
        float v = W[(size_t)n * RK + r];
        s += v * v;
    }
    __shared__ float red[256];
    red[tid] = s;
    __syncthreads();
    for (int st = 128; st > 0; st >>= 1) {
        if (tid < st) red[tid] += red[tid + st];
        __syncthreads();
    }
    __shared__ float invs;
    if (tid == 0) {
        float nm = sqrtf(red[0]);
        if (storeS) S[r] = nm;
        invs = 1.0f / (nm + 1e-8f);
    }
    __syncthreads();
    float iv = invs;
    float lmax = 0.f;
    for (int n = tid; n < nrows; n += 256) {
        float v = W[(size_t)n * RK + r] * iv;
        W[(size_t)n * RK + r] = v;
        lmax = fmaxf(lmax, fabsf(v));
    }
    if (storeS) {
        __syncthreads();
        red[tid] = lmax;
        __syncthreads();
        for (int st = 128; st > 0; st >>= 1) {
            if (tid < st) red[tid] = fmaxf(red[tid], red[tid + st]);
            __syncthreads();
        }
        if (tid == 0) atomicMax(&g_amax[2], __float_as_uint(red[0]));
    }
}

__global__ void k_amax(const float* __restrict__ p, int n, int slot) {
    float m = 0.f;
    for (int i = blockIdx.x * blockDim.x + threadIdx.x; i < n; i += gridDim.x * blockDim.x)
        m = fmaxf(m, fabsf(p[i]));
    __shared__ float red[256];
    red[threadIdx.x] = m;
    __syncthreads();
    for (int s = 128; s > 0; s >>= 1) {
        if (threadIdx.x < s) red[threadIdx.x] = fmaxf(red[threadIdx.x], red[threadIdx.x + s]);
        __syncthreads();
    }
    if (threadIdx.x == 0) atomicMax(&g_amax[slot], __float_as_uint(red[0]));
}

__global__ __launch_bounds__(256) void k_resid(const float* __restrict__ X,
                                               const float* __restrict__ U,
                                               const float* __restrict__ S,
                                               const float* __restrict__ V,
                                               float* __restrict__ R) {
    __shared__ __align__(16) float Ut[64][68];
    __shared__ __align__(16) float Vt[64][68];
    __shared__ float Ss[64];
    int m0 = blockIdx.x * 64, n0 = blockIdx.y * 64, tid = threadIdx.x;
    if (tid < 64) Ss[tid] = S[tid];
    __syncthreads();
    int row = tid >> 4, c4 = (tid & 15) * 4;
#pragma unroll
    for (int p = 0; p < 4; p++) {
        int rr = row + p * 16;
        float4 v = *(const float4*)&U[(size_t)(m0 + rr) * RK + c4];
        Ut[c4 + 0][rr] = v.x * Ss[c4 + 0];
        Ut[c4 + 1][rr] = v.y * Ss[c4 + 1];
        Ut[c4 + 2][rr] = v.z * Ss[c4 + 2];
        Ut[c4 + 3][rr] = v.w * Ss[c4 + 3];
        float4 w = *(const float4*)&V[(size_t)(n0 + rr) * RK + c4];
        Vt[c4 + 0][rr] = w.x; Vt[c4 + 1][rr] = w.y;
        Vt[c4 + 2][rr] = w.z; Vt[c4 + 3][rr] = w.w;
    }
    __syncthreads();
    int tm = tid >> 4, tn = tid & 15;
    float acc[4][4] = {};
#pragma unroll 8
    for (int k = 0; k < 64; k++) {
        float4 a = *(const float4*)&Ut[k][tm * 4];
        float4 b = *(const float4*)&Vt[k][tn * 4];
        float av[4] = {a.x, a.y, a.z, a.w}, bv[4] = {b.x, b.y, b.z, b.w};
#pragma unroll
        for (int i = 0; i < 4; i++)
#pragma unroll
            for (int j = 0; j < 4; j++) acc[i][j] += av[i] * bv[j];
    }
    float lmax = 0.f;
#pragma unroll
    for (int i = 0; i < 4; i++) {
        size_t off = (size_t)(m0 + tm * 4 + i) * DIN + n0 + tn * 4;
        float4 xv = *(const float4*)&X[off];
        float4 rv = make_float4(xv.x - acc[i][0], xv.y - acc[i][1],
                                xv.z - acc[i][2], xv.w - acc[i][3]);
        *(float4*)&R[off] = rv;
        lmax = fmaxf(lmax, fmaxf(fmaxf(fabsf(rv.x), fabsf(rv.y)),
                                 fmaxf(fabsf(rv.z), fabsf(rv.w))));
    }
    __shared__ float red[256];
    red[tid] = lmax;
    __syncthreads();
    for (int s = 128; s > 0; s >>= 1) {
        if (tid < s) red[tid] = fmaxf(red[tid], red[tid + s]);
        __syncthreads();
    }
    if (tid == 0) atomicMax(&g_amax[0], __float_as_uint(red[0]));
}

// ---------------- quantizers ----------------
__global__ void k_qbf(const float* __restrict__ src, __nv_bfloat16* __restrict__ dst,
                      int n4, int slot) {
    float s = getscale(slot);
    for (int i = blockIdx.x * blockDim.x + threadIdx.x; i < n4; i += gridDim.x * blockDim.x) {
        float4 v = ((const float4*)src)[i];
        __nv_bfloat162* d2 = (__nv_bfloat162*)dst;
        d2[i * 2 + 0] = __floats2bfloat162_rn(qlv(v.x, s), qlv(v.y, s));
        d2[i * 2 + 1] = __floats2bfloat162_rn(qlv(v.z, s), qlv(v.w, s));
    }
}
__global__ void k_qw(const float* __restrict__ src, char4* __restrict__ d8,
                     __nv_bfloat16* __restrict__ dbf, int n4) {
    float s = getscale(3);
    for (int i = blockIdx.x * blockDim.x + threadIdx.x; i < n4; i += gridDim.x * blockDim.x) {
        float4 v = ((const float4*)src)[i];
        int ix = qi8(v.x, s), iy = qi8(v.y, s), iz = qi8(v.z, s), iw = qi8(v.w, s);
        char4 c; c.x = (char)ix; c.y = (char)iy; c.z = (char)iz; c.w = (char)iw;
        d8[i] = c;
        __nv_bfloat162* d2 = (__nv_bfloat162*)dbf;
        d2[i * 2 + 0] = __floats2bfloat162_rn(0.5f * ix, 0.5f * iy);
        d2[i * 2 + 1] = __floats2bfloat162_rn(0.5f * iz, 0.5f * iw);
    }
}
__global__ void k_vq8(const float* __restrict__ V, int8_t* __restrict__ Vt8) {
    float s = getscale(2);
    for (int i = blockIdx.x * blockDim.x + threadIdx.x; i < DIN * RK; i += gridDim.x * blockDim.x) {
        int n = i >> 6, r = i & 63;
        Vt8[(size_t)r * DIN + n] = (int8_t)qi8(V[i], s);
    }
}

__global__ __launch_bounds__(256) void k_M(const int8_t* __restrict__ Wi8,
                                           const int8_t* __restrict__ Vt8,
                                           float* __restrict__ M) {
    __shared__ int Ws[4][1024];
    int j0 = blockIdx.x * 4, tid = threadIdx.x;
    {
        int rr = tid >> 6, t = tid & 63;
        const int4* src = (const int4*)(Wi8 + (size_t)(j0 + rr) * DIN);
#pragma unroll
        for (int q = 0; q < 4; q++) {
            int4 v = src[t + q * 64];
            *(int4*)&Ws[rr][(t + q * 64) * 4] = v;
        }
    }
    __syncthreads();
    int jl = tid & 3, r = tid >> 2;
    const int* vr = (const int*)(Vt8 + (size_t)r * DIN);
    int acc = 0;
    for (int k = 0; k < 1024; k++) acc = __dp4a(Ws[jl][k], vr[k], acc);
    float sc = getscale(3) * getscale(2) * 0.25f;
    M[(size_t)(j0 + jl) * RK + r] = (float)acc * sc;
}

__global__ void k_msplit(const float* __restrict__ M, const float* __restrict__ S,
                         __nv_bfloat16* __restrict__ Mhi, __nv_bfloat16* __restrict__ Mlo) {
    float f = getscale(1) / (getscale(0) * getscale(3));
    for (int i = blockIdx.x * blockDim.x + threadIdx.x; i < DOUT * RK;
         i += gridDim.x * blockDim.x) {
        float v = f * S[i & 63] * M[i];
        __nv_bfloat16 h = __float2bfloat16(v);
        Mhi[i] = h;
        Mlo[i] = __float2bfloat16(v - __bfloat162float(h));
    }
}

// out = bias + sc * [ Rbf@Wbf^T + UL@Mhi^T + UL@Mlo^T ]  (132 k-steps)
__global__ __launch_bounds__(256, 2) void k_hmma(const __nv_bfloat16* __restrict__ A,
                                                 const __nv_bfloat16* __restrict__ B,
                                                 const __nv_bfloat16* __restrict__ UL,
                                                 const __nv_bfloat16* __restrict__ Mhi,
                                                 const __nv_bfloat16* __restrict__ Mlo,
                                                 const float* __restrict__ bias,
                                                 float* __restrict__ C) {
    extern __shared__ __align__(16) char dsm[];
    uint32_t base = smem_u32(dsm);
    int tid = threadIdx.x, lane = tid & 31, wid = tid >> 5;
    int m0 = blockIdx.x * 128, j0 = blockIdx.y * 128;
    int wm = (wid & 1) * 64, wn = (wid >> 1) * 32;
    int g = lane >> 2, tg = (lane & 3) * 2;
    float acc[4][4][4] = {};

    int r0 = tid >> 2, r1 = r0 + 64;
    int segB = (tid & 3) * 16;
    const char* Ag = (const char*)A + (size_t)m0 * DIN * 2 + segB;
    const char* Bg = (const char*)B + (size_t)j0 * DIN * 2 + segB;
    const char* Ug = (const char*)UL + (size_t)m0 * 128 + segB;
    const char* Hg = (const char*)Mhi + (size_t)j0 * 128 + segB;
    const char* Lg = (const char*)Mlo + (size_t)j0 * 128 + segB;
    uint32_t sA0 = base + r0 * 80 + segB;
    uint32_t sA1 = base + r1 * 80 + segB;
    uint32_t sB0 = base + 40960 + r0 * 80 + segB;
    uint32_t sB1 = base + 40960 + r1 * 80 + segB;

    int rowA = wm + (lane & 7) + ((lane >> 3) & 1) * 8;
    uint32_t offA = base + rowA * 80 + ((lane >> 4) & 1) * 16;
    int rowB = wn + (lane & 7) + ((lane >> 4) & 1) * 8;
    uint32_t offB = base + 40960 + rowB * 80 + ((lane >> 3) & 1) * 16;

#define ISSUE_LOAD(ks) do {                                              \
    uint32_t _so = ((ks) & 3) * 10240;                                   \
    if ((ks) < 128) {                                                    \
        size_t _go = (size_t)(ks) * 64;                                  \
        cpa16(sA0 + _so, Ag + (size_t)r0 * (DIN * 2) + _go);             \
        cpa16(sA1 + _so, Ag + (size_t)r1 * (DIN * 2) + _go);             \
        cpa16(sB0 + _so, Bg + (size_t)r0 * (DIN * 2) + _go);             \
        cpa16(sB1 + _so, Bg + (size_t)r1 * (DIN * 2) + _go);             \
    } else {                                                             \
        int _t = (ks) - 128;                                             \
        size_t _co = (size_t)(_t & 1) * 64;                              \
        const char* _bm = (_t < 2) ? Hg : Lg;                            \
        cpa16(sA0 + _so, Ug + (size_t)r0 * 128 + _co);                   \
        cpa16(sA1 + _so, Ug + (size_t)r1 * 128 + _co);                   \
        cpa16(sB0 + _so, _bm + (size_t)r0 * 128 + _co);                  \
        cpa16(sB1 + _so, _bm + (size_t)r1 * 128 + _co);                  \
    }                                                                    \
} while (0)

    for (int p = 0; p < 3; p++) {
        ISSUE_LOAD(p);
        CPA_COMMIT();
    }

    for (int kt = 0; kt < 132; kt++) {
        int s = kt & 3;
        CPA_WAIT2();
        __syncthreads();
        uint32_t aS = offA + s * 10240;
        uint32_t bS = offB + s * 10240;
#pragma unroll
        for (int h = 0; h < 2; h++) {
            uint32_t af[4][4], bt[2][4];
#pragma unroll
            for (int mt = 0; mt < 4; mt++)
                ldsm4(af[mt], aS + mt * 1280 + h * 32);
            ldsm4(bt[0], bS + h * 32);
            ldsm4(bt[1], bS + 1280 + h * 32);
            uint32_t* bf[4] = {&bt[0][0], &bt[0][2], &bt[1][0], &bt[1][2]};
#pragma unroll
            for (int mt = 0; mt < 4; mt++)
#pragma unroll
                for (int nt = 0; nt < 4; nt++)
                    mma16816(acc[mt][nt], af[mt], bf[nt]);
        }
        if (kt + 3 < 132) ISSUE_LOAD(kt + 3);
        CPA_COMMIT();
        __syncthreads();
    }

    float sc = getscale(0) * getscale(3);
#pragma unroll
    for (int mt = 0; mt < 4; mt++) {
        int r = m0 + wm + mt * 16 + g;
#pragma unroll
        for (int nt = 0; nt < 4; nt++) {
            int col = j0 + wn + nt * 8 + tg;
            float2 bv = *(const float2*)&bias[col];
            float2 v0 = make_float2(bv.x + sc * acc[mt][nt][0],
                                    bv.y + sc * acc[mt][nt][1]);
            *(float2*)&C[(size_t)r * DOUT + col] = v0;
            float2 v1 = make_float2(bv.x + sc * acc[mt][nt][2],
                                    bv.y + sc * acc[mt][nt][3]);
            *(float2*)&C[(size_t)(r + 8) * DOUT + col] = v1;
        }
    }
}

extern "C" void kernel_launch(void* const* d_in, const int* in_sizes, int n_in,
                              void* d_out, int out_size) {
    const float* X = (const float*)d_in[0];
    const float* Wt = (const float*)d_in[1];
    const float* bias = (const float*)d_in[2];
    const float* V0 = (const float*)d_in[3];
    float* out = (float*)d_out;

    float *P, *Pp, *U, *Wm, *Wp, *Gp, *G, *Li, *S, *R, *M;
    int8_t *Wi8, *Vt8;
    __nv_bfloat16 *Rbf, *Wbf, *ULbf, *Mhi, *Mlo;
    cudaGetSymbolAddress((void**)&P, g_P);
    cudaGetSymbolAddress((void**)&Pp, g_Ppart);
    cudaGetSymbolAddress((void**)&U, g_U);
    cudaGetSymbolAddress((void**)&Wm, g_Wm);
    cudaGetSymbolAddress((void**)&Wp, g_Wpart);
    cudaGetSymbolAddress((void**)&Gp, g_Gp);
    cudaGetSymbolAddress((void**)&G, g_G);
    cudaGetSymbolAddress((void**)&Li, g_Linv);
    cudaGetSymbolAddress((void**)&S, g_S);
    cudaGetSymbolAddress((void**)&R, g_R);
    cudaGetSymbolAddress((void**)&M, g_M);
    cudaGetSymbolAddress((void**)&Wi8, g_Wi8);
    cudaGetSymbolAddress((void**)&Vt8, g_Vt8);
    cudaGetSymbolAddress((void**)&Rbf, g_Rbf);
    cudaGetSymbolAddress((void**)&Wbf, g_Wbf);
    cudaGetSymbolAddress((void**)&ULbf, g_ULbf);
    cudaGetSymbolAddress((void**)&Mhi, g_Mhi);
    cudaGetSymbolAddress((void**)&Mlo, g_Mlo);

    cudaFuncSetAttribute(k_hmma, cudaFuncAttributeMaxDynamicSharedMemorySize, 81920);

    k_init<<<1, 32>>>();
    const float* Bmat = V0;
    for (int it = 0; it < 2; it++) {
        k_xb<<<dim3(128, 4), 256>>>(X, Bmat, Pp);
        k_reduce<<<512, 256>>>(Pp, P, MR * RK, 4);
        k_gram<<<32, 256>>>(P, Gp);
        k_reduce<<<16, 256>>>(Gp, G, RK * RK, 32);
        k_chol<<<1, 64>>>(G, Li);
        k_applyr<<<128, 256>>>(P, Li, U, it);
        k_xtu<<<dim3(64, 8), 256>>>(X, U, Wp);
        k_reduce<<<256, 256>>>(Wp, Wm, DIN * RK, 8);
        k_colnorm<<<64, 256>>>(Wm, S, it, DIN);
        Bmat = Wm;
    }
    k_amax<<<1024, 256>>>(Wt, DOUT * DIN, 3);
    k_qbf<<<512, 256>>>(U, ULbf, MR * RK / 4, 1);
    k_vq8<<<256, 256>>>(Wm, Vt8);
    k_qw<<<1024, 256>>>(Wt, (char4*)Wi8, Wbf, DOUT * DIN / 4);
    k_resid<<<dim3(128, 64), 256>>>(X, U, S, Wm, R);
    k_qbf<<<2048, 256>>>(R, Rbf, MR * DIN / 4, 0);
    k_M<<<1024, 256>>>(Wi8, Vt8, M);
    k_msplit<<<256, 256>>>(M, S, Mhi, Mlo);
    k_hmma<<<dim3(64, 32), 256, 81920>>>(Rbf, Wbf, ULbf, Mhi, Mlo, bias, out);
}